// round 11
// baseline (speedup 1.0000x reference)
#include <cuda_runtime.h>

#define KCLS 256
#define WARPS_PER_BLOCK 8
#define THREADS (WARPS_PER_BLOCK * 32)
#define BLOCKS_RESIDENT 444   // 3 blocks/SM * 148 SMs

__device__ __forceinline__ float ex2f(float a) {
    float r; asm("ex2.approx.f32 %0, %1;" : "=f"(r) : "f"(a)); return r;
}
__device__ __forceinline__ float rcpf(float a) {
    float r; asm("rcp.approx.f32 %0, %1;" : "=f"(r) : "f"(a)); return r;
}

// 2 rows per warp: lanes 0-15 -> row A, lanes 16-31 -> row B.
// Each lane owns 16 consecutive classes. All warp-collectives width=16.
__global__ __launch_bounds__(THREADS, 3)
void dbf_kernel(const int* __restrict__ data,
                const float* __restrict__ t,
                const float4* __restrict__ noise,
                float4* __restrict__ out,
                int nrows)
{
    __shared__ __align__(16) float sg[KCLS];
    __shared__ __align__(16) float sh[KCLS];

    const int tid  = threadIdx.x;
    const int lane = tid & 31;
    const int warp = tid >> 5;
    const int half = lane >> 4;       // 0 = row A, 1 = row B
    const int sl   = lane & 15;       // sub-lane within 16-wide segment
    const int kb   = sl * 16;         // first class this lane owns

    // Closed-form Cholesky of C0 = (K+0.001) I - 11^T:
    //   T_k = a/(k-a), g_k = sqrt(a+T_k), h_k = T_k/g_k, a = K+0.001
    {
        const float ALPHA = 256.001f;
        float kf = (float)tid;
        float T  = ALPHA / (kf - ALPHA);
        float gg = sqrtf(ALPHA + T);
        sg[tid] = gg;
        sh[tid] = T / gg;
    }
    __syncthreads();

    // Tables to registers (same slice for both halves -> smem broadcast)
    float g[16], h[16];
    #pragma unroll
    for (int q = 0; q < 4; q++) {
        float4 gq = *(const float4*)&sg[kb + 4 * q];
        float4 hq = *(const float4*)&sh[kb + 4 * q];
        g[4*q+0] = gq.x; g[4*q+1] = gq.y; g[4*q+2] = gq.z; g[4*q+3] = gq.w;
        h[4*q+0] = hq.x; h[4*q+1] = hq.y; h[4*q+2] = hq.z; h[4*q+3] = hq.w;
    }

    const float L2E = 1.4426950408889634f;
    const int gw      = blockIdx.x * WARPS_PER_BLOCK + warp;   // pair index
    const int pstride = gridDim.x * WARPS_PER_BLOCK;
    const int npairs  = (nrows + 1) >> 1;
    if (gw >= npairs) return;
    const int niter = (npairs - gw + pstride - 1) / pstride;

    // This lane's row for iteration 0 (clamped for odd-nrows safety)
    int rowc = 2 * gw + half;
    const int row0 = rowc < nrows ? rowc : nrows - 1;

    const float*  tp = t + row0;
    const int*    dp = data + row0;
    const float4* np = noise + (size_t)row0 * (KCLS / 4) + sl * 4;
    float4*       op = out   + (size_t)row0 * (KCLS / 4) + sl * 4;
    const int    tstep = 2 * pstride;
    const size_t nstep = (size_t)2 * pstride * (KCLS / 4);

    // Prime pipeline: this row's loads in flight (4x LDG.128 = 64B/lane)
    float tv = __ldg(tp);
    int   x  = __ldg(dp);
    float4 v0 = __ldg(np + 0);
    float4 v1 = __ldg(np + 1);
    float4 v2 = __ldg(np + 2);
    float4 v3 = __ldg(np + 3);

    for (int it = 0; it < niter; it++) {
        const bool hn = (it + 1 < niter);
        float tv_n; int x_n; float4 w0, w1, w2, w3;
        if (hn) {
            tv_n = __ldg(tp + tstep);
            x_n  = __ldg(dp + tstep);
            w0 = __ldg(np + nstep + 0);
            w1 = __ldg(np + nstep + 1);
            w2 = __ldg(np + nstep + 2);
            w3 = __ldg(np + nstep + 3);
        }

        // Per-row scalars
        float sb = fminf(tv, 1.0f - 1e-6f);
        sb = fmaxf(sb, 1e-10f);
        const float sb2  = sb * L2E;
        const float kb2  = 256.0f * (sb * sb) * L2E;
        const float cofs = kb2 + 40.0f;   // softmax-invariant shift

        float vf[16];
        vf[0]=v0.x; vf[1]=v0.y; vf[2]=v0.z; vf[3]=v0.w;
        vf[4]=v1.x; vf[5]=v1.y; vf[6]=v1.z; vf[7]=v1.w;
        vf[8]=v2.x; vf[9]=v2.y; vf[10]=v2.z; vf[11]=v2.w;
        vf[12]=v3.x; vf[13]=v3.y; vf[14]=v3.z; vf[15]=v3.w;

        // Two independent 8-FMA chains (lo: 0-7, hi: 8-15 from zero);
        // hi's missing run_lo folded in later via c = sb2*run_lo.
        float runl = 0.0f, runh = 0.0f;
        float ml = -3.4e38f, mh = -3.4e38f;
        #pragma unroll
        for (int i = 0; i < 8; i++) {
            float a  = fmaf(g[i], vf[i], runl);
            float ti = fmaf(sb2, a, (kb + i == x) ? kb2 : 0.0f);
            runl = fmaf(h[i], vf[i], runl);
            vf[i] = ti;  ml = fmaxf(ml, ti);

            float b  = fmaf(g[i+8], vf[i+8], runh);
            float tj = fmaf(sb2, b, (kb + i + 8 == x) ? kb2 : 0.0f);
            runh = fmaf(h[i+8], vf[i+8], runh);
            vf[i+8] = tj;  mh = fmaxf(mh, tj);
        }
        const float c   = sb2 * runl;
        const float m   = fmaxf(ml, mh + c);   // true lane max of logits
        const float run = runl + runh;

        // Width-16 inclusive scan of lane totals (4 steps)
        float inc = run;
        #pragma unroll
        for (int d = 1; d < 16; d <<= 1) {
            float nb = __shfl_up_sync(0xFFFFFFFFu, inc, d, 16);
            if (sl >= d) inc += nb;
        }
        const float excl = inc - run;

        // Lane-local exp (overlaps scan latency); hi uses shifted subtrahend
        const float mhi = m - c;
        float sf = 0.0f;
        #pragma unroll
        for (int i = 0; i < 8; i++) {
            vf[i]   = ex2f(vf[i]   - m);
            vf[i+8] = ex2f(vf[i+8] - mhi);
            sf += vf[i] + vf[i+8];
        }

        // Stitch: e = f * 2^u, u = m + sb2*excl - cofs
        const float u  = fmaf(sb2, excl, m - cofs);
        const float wq = ex2f(u);
        float s = sf * wq;

        // Width-16 butterfly sum (4 steps)
        #pragma unroll
        for (int d = 8; d >= 1; d >>= 1)
            s += __shfl_xor_sync(0xFFFFFFFFu, s, d, 16);

        const float scale = wq * rcpf(s);
        if (rowc < nrows) {
            op[0] = make_float4(vf[0]*scale,  vf[1]*scale,  vf[2]*scale,  vf[3]*scale);
            op[1] = make_float4(vf[4]*scale,  vf[5]*scale,  vf[6]*scale,  vf[7]*scale);
            op[2] = make_float4(vf[8]*scale,  vf[9]*scale,  vf[10]*scale, vf[11]*scale);
            op[3] = make_float4(vf[12]*scale, vf[13]*scale, vf[14]*scale, vf[15]*scale);
        }

        // Rotate pipeline
        if (!hn) break;
        rowc += tstep;
        tp += tstep; dp += tstep; np += nstep; op += nstep;
        tv = tv_n; x = x_n; v0 = w0; v1 = w1; v2 = w2; v3 = w3;
    }
}

extern "C" void kernel_launch(void* const* d_in, const int* in_sizes, int n_in,
                              void* d_out, int out_size)
{
    const int*    data  = (const int*)d_in[0];
    const float*  t     = (const float*)d_in[1];
    const float4* noise = (const float4*)d_in[2];
    float4*       out   = (float4*)d_out;

    const int nrows  = in_sizes[0];          // B*S = 16384
    const int npairs = (nrows + 1) >> 1;
    int blocks = (npairs + WARPS_PER_BLOCK - 1) / WARPS_PER_BLOCK;
    if (blocks > BLOCKS_RESIDENT) blocks = BLOCKS_RESIDENT;
    dbf_kernel<<<blocks, THREADS>>>(data, t, noise, out, nrows);
}

// round 12
// speedup vs baseline: 1.4523x; 1.4523x over previous
#include <cuda_runtime.h>

#define KCLS 256
#define WARPS_PER_BLOCK 8
#define THREADS (WARPS_PER_BLOCK * 32)
#define BLOCKS_RESIDENT 592   // 4 blocks/SM * 148 SMs — best measured config

__device__ __forceinline__ float ex2f(float a) {
    float r; asm("ex2.approx.f32 %0, %1;" : "=f"(r) : "f"(a)); return r;
}
__device__ __forceinline__ float rcpf(float a) {
    float r; asm("rcp.approx.f32 %0, %1;" : "=f"(r) : "f"(a)); return r;
}

__global__ __launch_bounds__(THREADS, 4)
void dbf_kernel(const int* __restrict__ data,
                const float* __restrict__ t,
                const float4* __restrict__ noise,
                float4* __restrict__ out,
                int nrows)
{
    __shared__ __align__(16) float sg[KCLS];
    __shared__ __align__(16) float sr[KCLS];   // r_k = h_k/g_k = T/(a+T)

    const int tid  = threadIdx.x;
    const int lane = tid & 31;
    const int warp = tid >> 5;

    // Closed-form Cholesky of C0 = (K+0.001) I - 11^T:
    //   T_k = a/(k-a), g_k = sqrt(a+T_k), h_k = T_k/g_k, a = K+0.001
    {
        const float ALPHA = 256.001f;
        float kf = (float)tid;
        float T  = ALPHA / (kf - ALPHA);
        float gs = ALPHA + T;
        sg[tid] = sqrtf(gs);
        sr[tid] = T / gs;          // ratio h/g
    }
    __syncthreads();

    const int kbase = lane * 8;

    // g and ratio slices, register-resident for the whole loop
    float4 ga = *(const float4*)&sg[kbase];
    float4 gb = *(const float4*)&sg[kbase + 4];
    float4 ra = *(const float4*)&sr[kbase];
    float4 rb = *(const float4*)&sr[kbase + 4];
    const float rt[8] = {ra.x, ra.y, ra.z, ra.w, rb.x, rb.y, rb.z, rb.w};

    const float L2E = 1.4426950408889634f;
    const int stride = gridDim.x * WARPS_PER_BLOCK;
    const int gw = blockIdx.x * WARPS_PER_BLOCK + warp;
    if (gw >= nrows) return;

    const int niter = (nrows - gw + stride - 1) / stride;

    // Strided pointers — constant bumps per iteration
    const float*  tp = t + gw;
    const int*    dp = data + gw;
    const float4* np = noise + (size_t)gw * (KCLS / 4) + lane * 2;
    float4*       op = out   + (size_t)gw * (KCLS / 4) + lane * 2;
    const size_t  nstep = (size_t)stride * (KCLS / 4);

    // Prime pipeline
    float tv = __ldg(tp);
    int   x  = __ldg(dp);
    float4 n0 = __ldg(np + 0);
    float4 n1 = __ldg(np + 1);

    for (int it = 0; it < niter; it++) {
        // ---- Prefetch next row (constant-stride addresses) ----
        const bool hn = (it + 1 < niter);
        float tv_n; int x_n; float4 m0, m1;
        if (hn) {
            tv_n = __ldg(tp + stride);
            x_n  = __ldg(dp + stride);
            m0   = __ldg(np + nstep + 0);
            m1   = __ldg(np + nstep + 1);
        }

        // ---- Per-row scalars ----
        float sb = fminf(tv, 1.0f - 1e-6f);
        sb = fmaxf(sb, 1e-10f);
        const float sb2  = sb * L2E;                 // sb * log2(e)
        const float kb2  = 256.0f * (sb * sb) * L2E; // K*beta*log2(e)
        const float cofs = kb2 + 40.0f;              // softmax-invariant shift

        // gv only; h*v reconstructed as r*gv in the running sum
        float gv[8];
        gv[0] = ga.x * n0.x;  gv[1] = ga.y * n0.y;
        gv[2] = ga.z * n0.z;  gv[3] = ga.w * n0.w;
        gv[4] = gb.x * n1.x;  gv[5] = gb.y * n1.y;
        gv[6] = gb.z * n1.z;  gv[7] = gb.w * n1.w;

        // ---- Lane-local pass (no warp dependency; overlaps the scan) ----
        float f[8];
        float run = 0.0f;
        float m = -3.4e38f;
        #pragma unroll
        for (int i = 0; i < 8; i++) {
            float bias = (kbase + i == x) ? kb2 : 0.0f;
            float ti = fmaf(sb2, gv[i] + run, bias);
            run = fmaf(rt[i], gv[i], run);
            f[i] = ti;
            m = fmaxf(m, ti);
        }

        // ---- Warp inclusive scan of lane totals ----
        float inc = run;
        #pragma unroll
        for (int d = 1; d < 32; d <<= 1) {
            float nb = __shfl_up_sync(0xFFFFFFFFu, inc, d);
            if (lane >= d) inc += nb;
        }
        const float excl = inc - run;

        // ---- Lane-local exp (issues while scan drains) ----
        float sf = 0.0f;
        #pragma unroll
        for (int i = 0; i < 8; i++) {
            f[i] = ex2f(f[i] - m);   // in (0,1]
            sf += f[i];
        }

        // ---- Stitch: e_i = f_i * 2^u, u = m + sb2*excl - cofs (<= ~0) ----
        const float wq = ex2f(fmaf(sb2, excl, m - cofs));
        float s = sf * wq;

        // Warp sum
        #pragma unroll
        for (int d = 16; d >= 1; d >>= 1)
            s += __shfl_xor_sync(0xFFFFFFFFu, s, d);

        const float scale = wq * rcpf(s);
        op[0] = make_float4(f[0]*scale, f[1]*scale, f[2]*scale, f[3]*scale);
        op[1] = make_float4(f[4]*scale, f[5]*scale, f[6]*scale, f[7]*scale);

        // ---- Rotate pipeline (constant pointer bumps) ----
        if (!hn) break;
        tp += stride; dp += stride; np += nstep; op += nstep;
        tv = tv_n; x = x_n; n0 = m0; n1 = m1;
    }
}

extern "C" void kernel_launch(void* const* d_in, const int* in_sizes, int n_in,
                              void* d_out, int out_size)
{
    const int*    data  = (const int*)d_in[0];
    const float*  t     = (const float*)d_in[1];
    const float4* noise = (const float4*)d_in[2];
    float4*       out   = (float4*)d_out;

    const int nrows = in_sizes[0];   // B*S = 16384
    int blocks = (nrows + WARPS_PER_BLOCK - 1) / WARPS_PER_BLOCK;
    if (blocks > BLOCKS_RESIDENT) blocks = BLOCKS_RESIDENT;
    dbf_kernel<<<blocks, THREADS>>>(data, t, noise, out, nrows);
}